// round 16
// baseline (speedup 1.0000x reference)
#include <cuda_runtime.h>
#include <math.h>
#include <stdint.h>

// Problem constants
#define T_TOK 2048
#define H_DIM 2048
#define E_NUM 8
#define I_DIM 5632
#define N2I   (2 * I_DIM)
#define TOPK  2
#define R_NUM (T_TOK * TOPK)

// Tiling: CTA 128x256x64 (fp16), 16 warps (4x4), warp tile 32x64.
// Each 64-wide k-stage = two 32-wide sub-tiles in the proven R15 layout.
#define BM 128
#define BN 256
#define NTHR 512
#define A_SUB 8192                          // 128x32 fp16
#define B_SUB 16384                         // 256x32 fp16
#define SUB_BYTES (A_SUB + B_SUB)           // 24576
#define STAGE_BYTES (2 * SUB_BYTES)         // 49152 (BK=64)
#define STAGES 3
#define SMEM_BYTES (STAGES * STAGE_BYTES)   // 147456

// ---------------- device scratch ----------------
#define W13H_U32 (E_NUM * N2I * H_DIM / 2)
#define W2H_U32  (E_NUM * H_DIM * I_DIM / 2)
#define XH_U32   (T_TOK * H_DIM / 2)
__device__ uint32_t g_w13h[W13H_U32];          // fp16 weights (~369 MB)
__device__ uint32_t g_w2h[W2H_U32];            // (~185 MB)
__device__ uint32_t g_xh[XH_U32];              // fp16 x (8 MB)
__device__ uint32_t g_h2[(size_t)R_NUM * (I_DIM / 2)];  // fp16 h (~46 MB)
__device__ int   g_row_token[R_NUM];
__device__ float g_row_gate[R_NUM];
__device__ int   g_counts[E_NUM];
__device__ int   g_offsets[E_NUM];
__device__ int   g_tok_exp[R_NUM];
__device__ float g_tok_gate[R_NUM];

// ---------------- helpers ----------------
__device__ __forceinline__ uint32_t smem_u32(const void* p) {
    uint32_t a;
    asm("{ .reg .u64 t; cvta.to.shared.u64 t, %1; cvt.u32.u64 %0, t; }" : "=r"(a) : "l"(p));
    return a;
}
__device__ __forceinline__ uint32_t pack2(float lo, float hi) {
    uint32_t r;
    asm("cvt.rn.f16x2.f32 %0, %1, %2;" : "=r"(r) : "f"(hi), "f"(lo));
    return r;
}
__device__ __forceinline__ uint32_t swz64(uint32_t o) { return o ^ ((o >> 3) & 0x30); }

#define CPA(d, s, z) asm volatile("cp.async.cg.shared.global [%0], [%1], 16, %2;" :: "r"(d), "l"(s), "r"(z))
#define CPC() asm volatile("cp.async.commit_group;" ::: "memory")

#define LDSM4(r, a)                                                              \
    asm volatile("ldmatrix.sync.aligned.m8n8.x4.shared.b16 {%0,%1,%2,%3}, [%4];" \
                 : "=r"((r)[0]), "=r"((r)[1]), "=r"((r)[2]), "=r"((r)[3]) : "r"(a))

#define MMA_F16(ac, A, b0, b1)                                                   \
    asm volatile(                                                                \
        "mma.sync.aligned.m16n8k16.row.col.f32.f16.f16.f32 "                     \
        "{%0,%1,%2,%3},{%4,%5,%6,%7},{%8,%9},{%0,%1,%2,%3};"                     \
        : "+f"((ac)[0]), "+f"((ac)[1]), "+f"((ac)[2]), "+f"((ac)[3])             \
        : "r"((A)[0]), "r"((A)[1]), "r"((A)[2]), "r"((A)[3]), "r"(b0), "r"(b1))

// ---------------- routing ----------------
__global__ void k_route(const float* __restrict__ logits) {
    int t = blockIdx.x * blockDim.x + threadIdx.x;
    if (t >= T_TOK) return;
    float v[E_NUM];
    float mx = -1e30f;
#pragma unroll
    for (int e = 0; e < E_NUM; e++) { v[e] = logits[t * E_NUM + e]; mx = fmaxf(mx, v[e]); }
#pragma unroll
    for (int e = 0; e < E_NUM; e++) v[e] = __expf(v[e] - mx);
    int e1 = 0;
#pragma unroll
    for (int e = 1; e < E_NUM; e++) if (v[e] > v[e1]) e1 = e;
    int e2 = (e1 == 0) ? 1 : 0;
#pragma unroll
    for (int e = 0; e < E_NUM; e++) if (e != e1 && v[e] > v[e2]) e2 = e;
    float p1 = v[e1], p2 = v[e2];
    float inv = 1.0f / (p1 + p2);
    g_tok_exp[2 * t] = e1;  g_tok_exp[2 * t + 1] = e2;
    g_tok_gate[2 * t] = p1 * inv; g_tok_gate[2 * t + 1] = p2 * inv;
}

// single-block fused count + prefix + scatter
__global__ __launch_bounds__(1024) void k_count_scatter() {
    __shared__ int sc[E_NUM], so[E_NUM], sf[E_NUM];
    const int tid = threadIdx.x;
    if (tid < E_NUM) { sc[tid] = 0; sf[tid] = 0; }
    __syncthreads();
    for (int i = tid; i < R_NUM; i += blockDim.x)
        atomicAdd(&sc[g_tok_exp[i]], 1);
    __syncthreads();
    if (tid == 0) {
        int acc = 0;
        for (int e = 0; e < E_NUM; e++) {
            g_counts[e] = sc[e]; g_offsets[e] = acc; so[e] = acc; acc += sc[e];
        }
    }
    __syncthreads();
    for (int i = tid; i < R_NUM; i += blockDim.x) {
        const int e = g_tok_exp[i];
        const int pos = so[e] + atomicAdd(&sf[e], 1);
        g_row_token[pos] = i >> 1;
        g_row_gate[pos] = g_tok_gate[i];
    }
}

// ---------------- f32 -> f16 convert ----------------
__global__ __launch_bounds__(256) void k_cvt(const float4* __restrict__ s,
                                             uint2* __restrict__ d, int n4) {
    int i = blockIdx.x * blockDim.x + threadIdx.x;
    if (i >= n4) return;
    float4 v = s[i];
    uint2 o; o.x = pack2(v.x, v.y); o.y = pack2(v.z, v.w);
    d[i] = o;
}

// ---------------- fused GEMM (G=1: x@w13^T + silu*u -> g_h2 ; G=2: h@w2^T -> out) ----------------
template <int G>
__global__ __launch_bounds__(NTHR, 1) void k_gemm(const uint32_t* __restrict__ Ah,
                                                  const uint32_t* __restrict__ Bh,
                                                  float* __restrict__ out,
                                                  int ebase) {
    const int e = ebase + blockIdx.z;
    const int cnt = g_counts[e];
    const int rowt = blockIdx.x * BM;
    if (rowt >= cnt) return;
    const int base = g_offsets[e];
    const int i0 = blockIdx.y * 128;   // G==1
    const int n0 = blockIdx.y * BN;    // G==2

    extern __shared__ char smem[];
    const uint32_t sb = smem_u32(smem);
    const int tid = threadIdx.x;
    const int lane = tid & 31, wid = tid >> 5;
    const int lr = lane >> 2, cg = lane & 3;
    const int wm = wid >> 2;    // 0..3 : 32-row band
    const int wn = wid & 3;     // 0..3 : 64-col slice

    // ---- cp.async producer setup (per 32-wide sub-tile, R15-proven mapping) ----
    // A: thread t loads 16B: row = t>>2, chunk = t&3
    const int rA = tid >> 2;
    const int chA = tid & 3;
    const uint32_t aDst = swz64(rA * 64 + chA * 16);
    const uint32_t* aSrc;
    uint32_t aSz = 16;
    if (G == 1) {
        const int r = rowt + rA;
        const bool av = r < cnt;
        aSz = av ? 16u : 0u;
        const int tok = av ? g_row_token[base + r] : 0;
        aSrc = Ah + (size_t)tok * (H_DIM / 2) + chA * 4;
    } else {
        const int r = min(rowt + rA, cnt - 1);
        aSrc = g_h2 + (size_t)(base + r) * (I_DIM / 2) + chA * 4;
    }
    // B: thread t loads 32B: row = t>>1, chunks (t&1)*2, +1
    const int rB = tid >> 1;
    const int chB = (tid & 1) * 2;
    const uint32_t bDst0 = swz64(rB * 64 + chB * 16);
    const uint32_t bDst1 = swz64(rB * 64 + (chB + 1) * 16);
    const uint32_t* bSrc;
    if (G == 1) {
        const int gt = rB >> 3;   // even: gate, odd: up
        const int wr = i0 + (gt >> 1) * 8 + (rB & 7) + (gt & 1) * I_DIM;
        bSrc = Bh + (size_t)e * N2I * (H_DIM / 2) + (size_t)wr * (H_DIM / 2) + chB * 4;
    } else {
        bSrc = Bh + (size_t)e * H_DIM * (I_DIM / 2) + (size_t)(n0 + rB) * (I_DIM / 2) + chB * 4;
    }

    // ---- ldmatrix fragment addresses ----
    const int fr = (lane & 7) + ((lane >> 3) & 1) * 8;
    const int fc = lane >> 4;
    uint32_t aoff[2], boff[4];
#pragma unroll
    for (int mt = 0; mt < 2; mt++)
        aoff[mt] = swz64((uint32_t)((wm * 32 + mt * 16 + fr) * 64 + fc * 16));
#pragma unroll
    for (int g = 0; g < 4; g++)
        boff[g] = swz64((uint32_t)((wn * 64 + g * 16 + fr) * 64 + fc * 16));

    float acc[2][8][4];
#pragma unroll
    for (int mt = 0; mt < 2; mt++)
#pragma unroll
        for (int nt = 0; nt < 8; nt++)
#pragma unroll
            for (int c = 0; c < 4; c++) acc[mt][nt][c] = 0.f;

    const int NK = (G == 1 ? H_DIM : I_DIM) / 64;   // BK=64 iters

#define ISSUE(s_, it_)                                                           \
    do {                                                                         \
        const uint32_t sbase = sb + (s_) * STAGE_BYTES;                          \
        _Pragma("unroll")                                                        \
        for (int sub = 0; sub < 2; sub++) {                                      \
            const uint32_t subb = sbase + sub * SUB_BYTES;                       \
            const int ko = (it_) * 32 + sub * 16;                                \
            CPA(subb + aDst, aSrc + ko, aSz);                                    \
            const uint32_t bb = subb + A_SUB;                                    \
            CPA(bb + bDst0, bSrc + ko, 16);                                      \
            CPA(bb + bDst1, bSrc + ko + 4, 16);                                  \
        }                                                                        \
    } while (0)

    // prologue: fill stages 0 and 1 (NK >= 2 always)
    ISSUE(0, 0); CPC();
    ISSUE(1, 1); CPC();

    for (int it = 0; it < NK; it++) {
        asm volatile("cp.async.wait_group %0;" :: "n"(1) : "memory");
        __syncthreads();
        const uint32_t stbase = sb + (it % STAGES) * STAGE_BYTES;
#pragma unroll
        for (int sub = 0; sub < 2; sub++) {
            const uint32_t aB = stbase + sub * SUB_BYTES;
            const uint32_t bB = aB + A_SUB;
#pragma unroll
            for (int kk = 0; kk < 2; kk++) {
                uint32_t A4[2][4], B4[4][4];
#pragma unroll
                for (int mt = 0; mt < 2; mt++) LDSM4(A4[mt], aB + (aoff[mt] ^ (kk * 32)));
#pragma unroll
                for (int g = 0; g < 4; g++) LDSM4(B4[g], bB + (boff[g] ^ (kk * 32)));
#pragma unroll
                for (int mt = 0; mt < 2; mt++)
#pragma unroll
                    for (int g = 0; g < 4; g++) {
                        MMA_F16(acc[mt][2 * g],     A4[mt], B4[g][0], B4[g][2]);
                        MMA_F16(acc[mt][2 * g + 1], A4[mt], B4[g][1], B4[g][3]);
                    }
            }
        }
        if (it + 2 < NK) ISSUE((it + 2) % STAGES, it + 2);
        CPC();
    }
#undef ISSUE

    // ---- epilogues ----
    if (G == 1) {
#pragma unroll
        for (int mt = 0; mt < 2; mt++) {
#pragma unroll
            for (int rr = 0; rr < 2; rr++) {
                const int r = rowt + wm * 32 + mt * 16 + rr * 8 + lr;
                if (r < cnt) {
                    uint32_t* hrow = g_h2 + (size_t)(base + r) * (I_DIM / 2) + i0 / 2;
#pragma unroll
                    for (int q2 = 0; q2 < 4; q2++) {
                        const float g0 = acc[mt][2 * q2][rr * 2 + 0];
                        const float g1 = acc[mt][2 * q2][rr * 2 + 1];
                        const float u0 = acc[mt][2 * q2 + 1][rr * 2 + 0];
                        const float u1 = acc[mt][2 * q2 + 1][rr * 2 + 1];
                        const float h0 = (g0 / (1.f + __expf(-g0))) * u0;
                        const float h1 = (g1 / (1.f + __expf(-g1))) * u1;
                        hrow[(4 * wn + q2) * 4 + cg] = pack2(h0, h1);
                    }
                }
            }
        }
    } else {
#pragma unroll
        for (int mt = 0; mt < 2; mt++) {
#pragma unroll
            for (int rr = 0; rr < 2; rr++) {
                const int r = rowt + wm * 32 + mt * 16 + rr * 8 + lr;
                if (r < cnt) {
                    const int token = g_row_token[base + r];
                    const float gate = g_row_gate[base + r];
                    float* po = out + (size_t)token * H_DIM + n0 + wn * 64;
#pragma unroll
                    for (int nt = 0; nt < 8; nt++) {
                        const int col = nt * 8 + cg * 2;
                        atomicAdd(po + col,     gate * acc[mt][nt][rr * 2 + 0]);
                        atomicAdd(po + col + 1, gate * acc[mt][nt][rr * 2 + 1]);
                    }
                }
            }
        }
    }
}

// ---------------- launch ----------------
extern "C" void kernel_launch(void* const* d_in, const int* in_sizes, int n_in,
                              void* d_out, int out_size) {
    const float* x      = (const float*)d_in[0];
    const float* logits = (const float*)d_in[1];
    const float* w13    = (const float*)d_in[2];
    const float* w2     = (const float*)d_in[3];
    float* out = (float*)d_out;
    (void)in_sizes; (void)n_in;

    // one-time host-side resources
    static cudaStream_t s_side = nullptr;
    static cudaEvent_t s_fork = nullptr, s_join = nullptr, s_ev[4] = {};
    if (s_side == nullptr) {
        cudaStreamCreateWithFlags(&s_side, cudaStreamNonBlocking);
        cudaEventCreateWithFlags(&s_fork, cudaEventDisableTiming);
        cudaEventCreateWithFlags(&s_join, cudaEventDisableTiming);
        for (int q = 0; q < 4; q++) cudaEventCreateWithFlags(&s_ev[q], cudaEventDisableTiming);
    }
    cudaFuncSetAttribute(k_gemm<1>, cudaFuncAttributeMaxDynamicSharedMemorySize, SMEM_BYTES);
    cudaFuncSetAttribute(k_gemm<2>, cudaFuncAttributeMaxDynamicSharedMemorySize, SMEM_BYTES);

    uint32_t* w13h; cudaGetSymbolAddress((void**)&w13h, g_w13h);
    uint32_t* w2h;  cudaGetSymbolAddress((void**)&w2h,  g_w2h);
    uint32_t* xh;   cudaGetSymbolAddress((void**)&xh,   g_xh);
    const int n4_w13 = W13H_U32 / 2;
    const int n4_w2  = W2H_U32 / 2;
    const int n4_x   = XH_U32 / 2;
    const int n4_q   = n4_w13 / 4;          // per expert-pair quarter

    cudaEventRecord(s_fork, 0);

    // main: memset(1) route(2) count_scatter(3) cvt_x(4) gemm1c0(5)...
    cudaMemsetAsync(out, 0, (size_t)out_size * sizeof(float));
    k_route<<<T_TOK / 256, 256>>>(logits);
    k_count_scatter<<<1, 1024>>>();
    k_cvt<<<(n4_x + 255) / 256, 256>>>((const float4*)x, (uint2*)xh, n4_x);

    // side: w13 quarters (expert pairs), then w2
    cudaStreamWaitEvent(s_side, s_fork, 0);
    for (int q = 0; q < 4; q++) {
        k_cvt<<<(n4_q + 255) / 256, 256, 0, s_side>>>(
            (const float4*)(w13 + (size_t)q * n4_q * 4), (uint2*)(w13h + (size_t)q * n4_q * 2), n4_q);
        cudaEventRecord(s_ev[q], s_side);
    }
    k_cvt<<<(n4_w2 + 255) / 256, 256, 0, s_side>>>((const float4*)w2, (uint2*)w2h, n4_w2);
    cudaEventRecord(s_join, s_side);

    // main: gemm1 in 4 expert-pair chunks, each gated on its cvt chunk
    for (int q = 0; q < 4; q++) {
        cudaStreamWaitEvent(0, s_ev[q], 0);
        dim3 g1(R_NUM / BM, I_DIM / 128, 2);
        k_gemm<1><<<g1, NTHR, SMEM_BYTES>>>(xh, w13h, nullptr, 2 * q);
    }

    // gemm2 after all gemm1 (stream order) and w2 cvt (event)
    cudaStreamWaitEvent(0, s_join, 0);
    dim3 g2(R_NUM / BM, H_DIM / BN, E_NUM);
    k_gemm<2><<<g2, NTHR, SMEM_BYTES>>>(nullptr, w2h, out, 0);
}

// round 17
// speedup vs baseline: 1.0753x; 1.0753x over previous
#include <cuda_runtime.h>
#include <math.h>
#include <stdint.h>

// Problem constants
#define T_TOK 2048
#define H_DIM 2048
#define E_NUM 8
#define I_DIM 5632
#define N2I   (2 * I_DIM)
#define TOPK  2
#define R_NUM (T_TOK * TOPK)

// Tiling: CTA 128x256x32 (fp16), 16 warps (4x4), warp tile 32x64 (R15-proven)
#define BM 128
#define BN 256
#define BK 32
#define NTHR 512
#define STAGES 4
#define A_BYTES (BM * BK * 2)              // 8192
#define B_BYTES (BN * BK * 2)              // 16384
#define STAGE_BYTES (A_BYTES + B_BYTES)    // 24576
#define SMEM_BYTES (STAGES * STAGE_BYTES)  // 98304

// ---------------- device scratch ----------------
#define W13H_U32 (E_NUM * N2I * H_DIM / 2)
#define W2H_U32  (E_NUM * H_DIM * I_DIM / 2)
#define XH_U32   (T_TOK * H_DIM / 2)
__device__ uint32_t g_w13h[W13H_U32];          // fp16 weights (~369 MB)
__device__ uint32_t g_w2h[W2H_U32];            // (~185 MB)
__device__ uint32_t g_xh[XH_U32];              // fp16 x (8 MB)
__device__ uint32_t g_h2[(size_t)R_NUM * (I_DIM / 2)];  // fp16 h (~46 MB)
__device__ int   g_row_token[R_NUM];
__device__ float g_row_gate[R_NUM];
__device__ int   g_counts[E_NUM];
__device__ int   g_offsets[E_NUM];
__device__ int   g_tok_exp[R_NUM];
__device__ float g_tok_gate[R_NUM];

// ---------------- helpers ----------------
__device__ __forceinline__ uint32_t smem_u32(const void* p) {
    uint32_t a;
    asm("{ .reg .u64 t; cvta.to.shared.u64 t, %1; cvt.u32.u64 %0, t; }" : "=r"(a) : "l"(p));
    return a;
}
__device__ __forceinline__ uint32_t pack2(float lo, float hi) {
    uint32_t r;
    asm("cvt.rn.f16x2.f32 %0, %1, %2;" : "=r"(r) : "f"(hi), "f"(lo));
    return r;
}
__device__ __forceinline__ uint32_t swz64(uint32_t o) { return o ^ ((o >> 3) & 0x30); }

#define CPA(d, s, z) asm volatile("cp.async.cg.shared.global [%0], [%1], 16, %2;" :: "r"(d), "l"(s), "r"(z))
#define CPC() asm volatile("cp.async.commit_group;" ::: "memory")

#define LDSM4(r, a)                                                              \
    asm volatile("ldmatrix.sync.aligned.m8n8.x4.shared.b16 {%0,%1,%2,%3}, [%4];" \
                 : "=r"((r)[0]), "=r"((r)[1]), "=r"((r)[2]), "=r"((r)[3]) : "r"(a))

#define MMA_F16(ac, A, b0, b1)                                                   \
    asm volatile(                                                                \
        "mma.sync.aligned.m16n8k16.row.col.f32.f16.f16.f32 "                     \
        "{%0,%1,%2,%3},{%4,%5,%6,%7},{%8,%9},{%0,%1,%2,%3};"                     \
        : "+f"((ac)[0]), "+f"((ac)[1]), "+f"((ac)[2]), "+f"((ac)[3])             \
        : "r"((A)[0]), "r"((A)[1]), "r"((A)[2]), "r"((A)[3]), "r"(b0), "r"(b1))

// ---------------- routing ----------------
__global__ void k_route(const float* __restrict__ logits) {
    int t = blockIdx.x * blockDim.x + threadIdx.x;
    if (t >= T_TOK) return;
    float v[E_NUM];
    float mx = -1e30f;
#pragma unroll
    for (int e = 0; e < E_NUM; e++) { v[e] = logits[t * E_NUM + e]; mx = fmaxf(mx, v[e]); }
#pragma unroll
    for (int e = 0; e < E_NUM; e++) v[e] = __expf(v[e] - mx);
    int e1 = 0;
#pragma unroll
    for (int e = 1; e < E_NUM; e++) if (v[e] > v[e1]) e1 = e;
    int e2 = (e1 == 0) ? 1 : 0;
#pragma unroll
    for (int e = 0; e < E_NUM; e++) if (e != e1 && v[e] > v[e2]) e2 = e;
    float p1 = v[e1], p2 = v[e2];
    float inv = 1.0f / (p1 + p2);
    g_tok_exp[2 * t] = e1;  g_tok_exp[2 * t + 1] = e2;
    g_tok_gate[2 * t] = p1 * inv; g_tok_gate[2 * t + 1] = p2 * inv;
}

// single-block fused count + prefix + scatter
__global__ __launch_bounds__(1024) void k_count_scatter() {
    __shared__ int sc[E_NUM], so[E_NUM], sf[E_NUM];
    const int tid = threadIdx.x;
    if (tid < E_NUM) { sc[tid] = 0; sf[tid] = 0; }
    __syncthreads();
    for (int i = tid; i < R_NUM; i += blockDim.x)
        atomicAdd(&sc[g_tok_exp[i]], 1);
    __syncthreads();
    if (tid == 0) {
        int acc = 0;
        for (int e = 0; e < E_NUM; e++) {
            g_counts[e] = sc[e]; g_offsets[e] = acc; so[e] = acc; acc += sc[e];
        }
    }
    __syncthreads();
    for (int i = tid; i < R_NUM; i += blockDim.x) {
        const int e = g_tok_exp[i];
        const int pos = so[e] + atomicAdd(&sf[e], 1);
        g_row_token[pos] = i >> 1;
        g_row_gate[pos] = g_tok_gate[i];
    }
}

// ---------------- f32 -> f16 convert ----------------
__global__ __launch_bounds__(256) void k_cvt(const float4* __restrict__ s,
                                             uint2* __restrict__ d, int n4) {
    int i = blockIdx.x * blockDim.x + threadIdx.x;
    if (i >= n4) return;
    float4 v = s[i];
    uint2 o; o.x = pack2(v.x, v.y); o.y = pack2(v.z, v.w);
    d[i] = o;
}

// ---------------- fused GEMM (G=1: x@w13^T + silu*u -> g_h2 ; G=2: h@w2^T -> out) ----------------
template <int G>
__global__ __launch_bounds__(NTHR, 1) void k_gemm(const uint32_t* __restrict__ Ah,
                                                  const uint32_t* __restrict__ Bh,
                                                  float* __restrict__ out,
                                                  int ebase) {
    const int e = ebase + blockIdx.z;
    const int cnt = g_counts[e];
    const int rowt = blockIdx.x * BM;
    if (rowt >= cnt) return;
    const int base = g_offsets[e];
    const int i0 = blockIdx.y * 128;   // G==1
    const int n0 = blockIdx.y * BN;    // G==2

    extern __shared__ char smem[];
    const uint32_t sb = smem_u32(smem);
    const int tid = threadIdx.x;
    const int lane = tid & 31, wid = tid >> 5;
    const int lr = lane >> 2, cg = lane & 3;
    const int wm = wid >> 2;    // 0..3 : 32-row band
    const int wn = wid & 3;     // 0..3 : 64-col slice

    // ---- cp.async producer setup ----
    const int rA = tid >> 2;
    const int chA = tid & 3;
    const uint32_t aDst = swz64(rA * 64 + chA * 16);
    const uint32_t* aSrc;
    uint32_t aSz = 16;
    if (G == 1) {
        const int r = rowt + rA;
        const bool av = r < cnt;
        aSz = av ? 16u : 0u;
        const int tok = av ? g_row_token[base + r] : 0;
        aSrc = Ah + (size_t)tok * (H_DIM / 2) + chA * 4;
    } else {
        const int r = min(rowt + rA, cnt - 1);
        aSrc = g_h2 + (size_t)(base + r) * (I_DIM / 2) + chA * 4;
    }
    const int rB = tid >> 1;
    const int chB = (tid & 1) * 2;
    const uint32_t bDst0 = swz64(rB * 64 + chB * 16);
    const uint32_t bDst1 = swz64(rB * 64 + (chB + 1) * 16);
    const uint32_t* bSrc;
    if (G == 1) {
        const int gt = rB >> 3;   // even: gate, odd: up
        const int wr = i0 + (gt >> 1) * 8 + (rB & 7) + (gt & 1) * I_DIM;
        bSrc = Bh + (size_t)e * N2I * (H_DIM / 2) + (size_t)wr * (H_DIM / 2) + chB * 4;
    } else {
        bSrc = Bh + (size_t)e * H_DIM * (I_DIM / 2) + (size_t)(n0 + rB) * (I_DIM / 2) + chB * 4;
    }

    // ---- ldmatrix fragment addresses ----
    const int fr = (lane & 7) + ((lane >> 3) & 1) * 8;
    const int fc = lane >> 4;
    uint32_t aoff[2], boff[4];
#pragma unroll
    for (int mt = 0; mt < 2; mt++)
        aoff[mt] = swz64((uint32_t)((wm * 32 + mt * 16 + fr) * 64 + fc * 16));
#pragma unroll
    for (int g = 0; g < 4; g++)
        boff[g] = swz64((uint32_t)((wn * 64 + g * 16 + fr) * 64 + fc * 16));

    float acc[2][8][4];
#pragma unroll
    for (int mt = 0; mt < 2; mt++)
#pragma unroll
        for (int nt = 0; nt < 8; nt++)
#pragma unroll
            for (int c = 0; c < 4; c++) acc[mt][nt][c] = 0.f;

    const int NK = (G == 1 ? H_DIM : I_DIM) / BK;

#define ISSUE(s_, it_)                                                           \
    do {                                                                         \
        const uint32_t sbase = sb + (s_) * STAGE_BYTES;                          \
        CPA(sbase + aDst, aSrc + (it_) * (BK / 2), aSz);                         \
        const uint32_t* bs = bSrc + (it_) * (BK / 2);                            \
        const uint32_t bb = sbase + A_BYTES;                                     \
        CPA(bb + bDst0, bs, 16);                                                 \
        CPA(bb + bDst1, bs + 4, 16);                                             \
    } while (0)

    // prologue: fill stages 0..STAGES-2
#pragma unroll
    for (int s = 0; s < STAGES - 1; s++) {
        if (s < NK) ISSUE(s, s);
        CPC();
    }

    for (int it = 0; it < NK; it++) {
        asm volatile("cp.async.wait_group %0;" :: "n"(STAGES - 2) : "memory");
        __syncthreads();
        const uint32_t aB = sb + (it % STAGES) * STAGE_BYTES;
        const uint32_t bB = aB + A_BYTES;
#pragma unroll
        for (int kk = 0; kk < 2; kk++) {
            uint32_t A4[2][4], B4[4][4];
#pragma unroll
            for (int mt = 0; mt < 2; mt++) LDSM4(A4[mt], aB + (aoff[mt] ^ (kk * 32)));
#pragma unroll
            for (int g = 0; g < 4; g++) LDSM4(B4[g], bB + (boff[g] ^ (kk * 32)));
#pragma unroll
            for (int mt = 0; mt < 2; mt++)
#pragma unroll
                for (int g = 0; g < 4; g++) {
                    MMA_F16(acc[mt][2 * g],     A4[mt], B4[g][0], B4[g][2]);
                    MMA_F16(acc[mt][2 * g + 1], A4[mt], B4[g][1], B4[g][3]);
                }
        }
        if (it + STAGES - 1 < NK) ISSUE((it + STAGES - 1) % STAGES, it + STAGES - 1);
        CPC();
    }
#undef ISSUE

    // ---- epilogues ----
    if (G == 1) {
#pragma unroll
        for (int mt = 0; mt < 2; mt++) {
#pragma unroll
            for (int rr = 0; rr < 2; rr++) {
                const int r = rowt + wm * 32 + mt * 16 + rr * 8 + lr;
                if (r < cnt) {
                    uint32_t* hrow = g_h2 + (size_t)(base + r) * (I_DIM / 2) + i0 / 2;
#pragma unroll
                    for (int q2 = 0; q2 < 4; q2++) {
                        const float g0 = acc[mt][2 * q2][rr * 2 + 0];
                        const float g1 = acc[mt][2 * q2][rr * 2 + 1];
                        const float u0 = acc[mt][2 * q2 + 1][rr * 2 + 0];
                        const float u1 = acc[mt][2 * q2 + 1][rr * 2 + 1];
                        const float h0 = (g0 / (1.f + __expf(-g0))) * u0;
                        const float h1 = (g1 / (1.f + __expf(-g1))) * u1;
                        hrow[(4 * wn + q2) * 4 + cg] = pack2(h0, h1);
                    }
                }
            }
        }
    } else {
#pragma unroll
        for (int mt = 0; mt < 2; mt++) {
#pragma unroll
            for (int rr = 0; rr < 2; rr++) {
                const int r = rowt + wm * 32 + mt * 16 + rr * 8 + lr;
                if (r < cnt) {
                    const int token = g_row_token[base + r];
                    const float gate = g_row_gate[base + r];
                    float* po = out + (size_t)token * H_DIM + n0 + wn * 64;
#pragma unroll
                    for (int nt = 0; nt < 8; nt++) {
                        const int col = nt * 8 + cg * 2;
                        atomicAdd(po + col,     gate * acc[mt][nt][rr * 2 + 0]);
                        atomicAdd(po + col + 1, gate * acc[mt][nt][rr * 2 + 1]);
                    }
                }
            }
        }
    }
}

// ---------------- launch ----------------
extern "C" void kernel_launch(void* const* d_in, const int* in_sizes, int n_in,
                              void* d_out, int out_size) {
    const float* x      = (const float*)d_in[0];
    const float* logits = (const float*)d_in[1];
    const float* w13    = (const float*)d_in[2];
    const float* w2     = (const float*)d_in[3];
    float* out = (float*)d_out;
    (void)in_sizes; (void)n_in;

    // one-time host-side resources
    static cudaStream_t s_side = nullptr;
    static cudaEvent_t s_fork = nullptr, s_join = nullptr, s_ev[2] = {};
    if (s_side == nullptr) {
        cudaStreamCreateWithFlags(&s_side, cudaStreamNonBlocking);
        cudaEventCreateWithFlags(&s_fork, cudaEventDisableTiming);
        cudaEventCreateWithFlags(&s_join, cudaEventDisableTiming);
        for (int q = 0; q < 2; q++) cudaEventCreateWithFlags(&s_ev[q], cudaEventDisableTiming);
    }
    cudaFuncSetAttribute(k_gemm<1>, cudaFuncAttributeMaxDynamicSharedMemorySize, SMEM_BYTES);
    cudaFuncSetAttribute(k_gemm<2>, cudaFuncAttributeMaxDynamicSharedMemorySize, SMEM_BYTES);

    uint32_t* w13h; cudaGetSymbolAddress((void**)&w13h, g_w13h);
    uint32_t* w2h;  cudaGetSymbolAddress((void**)&w2h,  g_w2h);
    uint32_t* xh;   cudaGetSymbolAddress((void**)&xh,   g_xh);
    const int n4_w13 = W13H_U32 / 2;
    const int n4_w2  = W2H_U32 / 2;
    const int n4_x   = XH_U32 / 2;
    const int n4_h   = n4_w13 / 2;          // 4-expert half

    cudaEventRecord(s_fork, 0);

    // main: memset, route, count_scatter, x cvt (small)
    cudaMemsetAsync(out, 0, (size_t)out_size * sizeof(float));
    k_route<<<T_TOK / 256, 256>>>(logits);
    k_count_scatter<<<1, 1024>>>();
    k_cvt<<<(n4_x + 255) / 256, 256>>>((const float4*)x, (uint2*)xh, n4_x);

    // side: w13 halves (experts 0-3, 4-7), then w2
    cudaStreamWaitEvent(s_side, s_fork, 0);
    for (int q = 0; q < 2; q++) {
        k_cvt<<<(n4_h + 255) / 256, 256, 0, s_side>>>(
            (const float4*)(w13 + (size_t)q * n4_h * 4), (uint2*)(w13h + (size_t)q * n4_h * 2), n4_h);
        cudaEventRecord(s_ev[q], s_side);
    }
    k_cvt<<<(n4_w2 + 255) / 256, 256, 0, s_side>>>((const float4*)w2, (uint2*)w2h, n4_w2);
    cudaEventRecord(s_join, s_side);

    // main: gemm1 in 2 chunks of 4 experts, each gated on its cvt half
    for (int q = 0; q < 2; q++) {
        cudaStreamWaitEvent(0, s_ev[q], 0);
        dim3 g1(R_NUM / BM, I_DIM / 128, 4);
        k_gemm<1><<<g1, NTHR, SMEM_BYTES>>>(xh, w13h, nullptr, 4 * q);
    }

    // gemm2 after all gemm1 (stream order) and w2 cvt (event)
    cudaStreamWaitEvent(0, s_join, 0);
    dim3 g2(R_NUM / BM, H_DIM / BN, E_NUM);
    k_gemm<2><<<g2, NTHR, SMEM_BYTES>>>(nullptr, w2h, out, 0);
}